// round 1
// baseline (speedup 1.0000x reference)
#include <cuda_runtime.h>
#include <cuda_fp16.h>
#include <mma.h>

using namespace nvcuda;

#define NTOK 8192
#define DIM  2048
#define HID  1024
#define NEXP 8
#define SHID 2048

// ---------------- scratch (device globals; no allocations) ----------------
__device__ __half g_xh  [(size_t)NTOK * DIM];        // fp16 copy of x
__device__ __half g_w1h [(size_t)NEXP * DIM * HID];  // scaled x1024
__device__ __half g_w2h [(size_t)NEXP * HID * DIM];
__device__ __half g_sw1h[(size_t)DIM * SHID];
__device__ __half g_sw2h[(size_t)SHID * DIM];
__device__ __half g_hsh [(size_t)NTOK * SHID];       // gelu(x@sw1+sb1) fp16
__device__ __half g_hr  [(size_t)2 * NTOK * HID];    // routed hidden, [slot][token][HID]
__device__ float  g_rout[(size_t)2 * NTOK * DIM];    // routed out, [slot][token][DIM]
__device__ int    g_cnt [NEXP];
__device__ int    g_list[NEXP * NTOK];               // entry = token*2 + slot
__device__ float  g_gate[NEXP * NTOK];

// ---------------- small helpers ----------------
__device__ __forceinline__ float gelu_f(float v) {
    return 0.5f * v * (1.0f + erff(v * 0.70710678118654752f));
}

__global__ void zero_cnt_kernel() {
    if (threadIdx.x < NEXP) g_cnt[threadIdx.x] = 0;
}

// ---------------- fp32 -> fp16 conversion kernels ----------------
#define CONV_KERNEL(NAME, DST, NTOT, SCALE)                                      \
__global__ void NAME(const float* __restrict__ src) {                            \
    size_t i = (size_t)blockIdx.x * blockDim.x + threadIdx.x;                    \
    size_t st = (size_t)gridDim.x * blockDim.x;                                  \
    for (; i < (size_t)(NTOT); i += st) DST[i] = __float2half(src[i] * (SCALE)); \
}

CONV_KERNEL(conv_x,   g_xh,   (size_t)NTOK*DIM,      1.0f)
CONV_KERNEL(conv_w1,  g_w1h,  (size_t)NEXP*DIM*HID,  1024.0f)
CONV_KERNEL(conv_w2,  g_w2h,  (size_t)NEXP*HID*DIM,  1024.0f)
CONV_KERNEL(conv_sw1, g_sw1h, (size_t)DIM*SHID,      1024.0f)
CONV_KERNEL(conv_sw2, g_sw2h, (size_t)SHID*DIM,      1024.0f)

// ---------------- gating: fp32 logits, top-2, softmax, list build ----------------
__global__ void gating_kernel(const float* __restrict__ x,
                              const float* __restrict__ gw) {
    int token = blockIdx.x * 8 + (threadIdx.x >> 5);
    int lane  = threadIdx.x & 31;
    if (token >= NTOK) return;

    const float* xr = x + (size_t)token * DIM;
    float acc[NEXP];
    #pragma unroll
    for (int e = 0; e < NEXP; e++) acc[e] = 0.0f;

    for (int d = lane; d < DIM; d += 32) {
        float xv = xr[d];
        const float* g = gw + (size_t)d * NEXP;
        #pragma unroll
        for (int e = 0; e < NEXP; e++) acc[e] += xv * g[e];
    }
    #pragma unroll
    for (int e = 0; e < NEXP; e++) {
        #pragma unroll
        for (int o = 16; o > 0; o >>= 1)
            acc[e] += __shfl_down_sync(0xFFFFFFFFu, acc[e], o);
    }

    if (lane == 0) {
        float m1 = -1e30f, m2 = -1e30f;
        int i1 = 0, i2 = 0;
        #pragma unroll
        for (int e = 0; e < NEXP; e++) {
            float v = acc[e];
            if (v > m1) { m2 = m1; i2 = i1; m1 = v; i1 = e; }
            else if (v > m2) { m2 = v; i2 = e; }
        }
        float g0 = 1.0f / (1.0f + expf(m2 - m1));  // softmax over [m1, m2]
        float g1 = 1.0f - g0;

        int p0 = atomicAdd(&g_cnt[i1], 1);
        g_list[i1 * NTOK + p0] = token * 2 + 0;
        g_gate[i1 * NTOK + p0] = g0;
        int p1 = atomicAdd(&g_cnt[i2], 1);
        g_list[i2 * NTOK + p1] = token * 2 + 1;
        g_gate[i2 * NTOK + p1] = g1;
    }
}

// ---------------- wmma GEMM ----------------
// MODE 0: shared layer1:  A=g_xh  [8192,2048], B=g_sw1h [2048,2048] -> gelu -> g_hsh (fp16)
// MODE 1: shared layer2:  A=g_hsh [8192,2048], B=g_sw2h [2048,2048] -> +sb2 -> d_out (fp32)
// MODE 2: routed layer1:  A=gather(g_xh),      B=g_w1h[e][2048,1024] -> gelu -> g_hr (fp16)
// MODE 3: routed layer2:  A=gather(g_hr),      B=g_w2h[e][1024,2048] -> gate*(acc+b2) -> g_rout
#define BM 128
#define BN 128
#define SA_LD 72
#define SB_LD 136

template<int MODE>
__global__ __launch_bounds__(256)
void gemm_wmma(const float* __restrict__ bias, float* __restrict__ outp) {
    __shared__ __align__(32) __half sA[BM * SA_LD];
    __shared__ __align__(32) __half sB[64 * SB_LD];
    __shared__ const __half* sRow[BM];
    __shared__ unsigned int  sEnt[BM];
    __shared__ float         sGate[BM];

    const int tid    = threadIdx.x;
    const int warpId = tid >> 5;
    const int lane   = tid & 31;

    int e = 0;
    int cnt = NTOK;
    if (MODE >= 2) {
        e = blockIdx.z;
        cnt = g_cnt[e];
        if ((int)blockIdx.x * BM >= cnt) return;
    }
    const int rowBase = blockIdx.x * BM;
    const int colBase = blockIdx.y * BN;

    int K, ldb;
    const __half* Bmat;
    if (MODE == 0) { K = DIM; ldb = SHID; Bmat = g_sw1h; }
    if (MODE == 1) { K = SHID; ldb = DIM; Bmat = g_sw2h; }
    if (MODE == 2) { K = DIM; ldb = HID; Bmat = g_w1h + (size_t)e * DIM * HID; }
    if (MODE == 3) { K = HID; ldb = DIM; Bmat = g_w2h + (size_t)e * HID * DIM; }

    // per-row source pointers + epilogue metadata
    for (int r = tid; r < BM; r += 256) {
        int row = rowBase + r;
        if (MODE == 0)      sRow[r] = g_xh  + (size_t)row * DIM;
        else if (MODE == 1) sRow[r] = g_hsh + (size_t)row * SHID;
        else {
            if (row < cnt) {
                int entry = g_list[e * NTOK + row];
                int token = entry >> 1, slot = entry & 1;
                if (MODE == 2) sRow[r] = g_xh + (size_t)token * DIM;
                else           sRow[r] = g_hr + ((size_t)slot * NTOK + token) * HID;
                sEnt[r] = (unsigned)entry;
                if (MODE == 3) sGate[r] = g_gate[e * NTOK + row];
            } else {
                sRow[r] = nullptr;
            }
        }
    }
    __syncthreads();

    wmma::fragment<wmma::accumulator, 16, 16, 16, float> acc[2][4];
    #pragma unroll
    for (int mi = 0; mi < 2; mi++)
        #pragma unroll
        for (int ni = 0; ni < 4; ni++)
            wmma::fill_fragment(acc[mi][ni], 0.0f);

    const int wm = warpId >> 1;  // 0..3
    const int wn = warpId & 1;   // 0..1

    for (int kt = 0; kt < K; kt += 64) {
        // A tile: 128 x 64 halves, int4 vector loads, gather via sRow
        #pragma unroll
        for (int it = 0; it < 4; it++) {
            int idx = tid + it * 256;
            int ar = idx >> 3, c8 = idx & 7;
            const __half* p = sRow[ar];
            int4 v = make_int4(0, 0, 0, 0);
            if (MODE < 2 || p) v = *(const int4*)(p + kt + c8 * 8);
            *(int4*)(sA + ar * SA_LD + c8 * 8) = v;
        }
        // B tile: 64 x 128 halves
        #pragma unroll
        for (int it = 0; it < 4; it++) {
            int idx = tid + it * 256;
            int br = idx >> 4, c8 = idx & 15;
            *(int4*)(sB + br * SB_LD + c8 * 8) =
                *(const int4*)(Bmat + (size_t)(kt + br) * ldb + colBase + c8 * 8);
        }
        __syncthreads();

        #pragma unroll
        for (int ks = 0; ks < 4; ks++) {
            wmma::fragment<wmma::matrix_a, 16, 16, 16, __half, wmma::row_major> fa[2];
            wmma::fragment<wmma::matrix_b, 16, 16, 16, __half, wmma::row_major> fb[4];
            #pragma unroll
            for (int mi = 0; mi < 2; mi++)
                wmma::load_matrix_sync(fa[mi], sA + (wm * 32 + mi * 16) * SA_LD + ks * 16, SA_LD);
            #pragma unroll
            for (int ni = 0; ni < 4; ni++)
                wmma::load_matrix_sync(fb[ni], sB + (ks * 16) * SB_LD + wn * 64 + ni * 16, SB_LD);
            #pragma unroll
            for (int mi = 0; mi < 2; mi++)
                #pragma unroll
                for (int ni = 0; ni < 4; ni++)
                    wmma::mma_sync(acc[mi][ni], fa[mi], fb[ni], acc[mi][ni]);
        }
        __syncthreads();
    }

    // epilogue: stage through smem (reuse sB), apply bias/gelu/gate, store
    float* stage   = (float*)sB;
    float* myStage = stage + warpId * 16 * 20;
    const float invS = 1.0f / 1024.0f;  // undo weight scaling

    #pragma unroll
    for (int mi = 0; mi < 2; mi++) {
        #pragma unroll
        for (int ni = 0; ni < 4; ni++) {
            wmma::store_matrix_sync(myStage, acc[mi][ni], 20, wmma::mem_row_major);
            __syncwarp();
            #pragma unroll
            for (int t = lane; t < 256; t += 32) {
                int r = t >> 4, c = t & 15;
                int lr  = wm * 32 + mi * 16 + r;
                int row = rowBase + lr;
                int col = colBase + wn * 64 + ni * 16 + c;
                bool valid = (MODE < 2) || (row < cnt);
                if (valid) {
                    float bofs;
                    if (MODE == 2)      bofs = bias[e * HID + col];
                    else if (MODE == 3) bofs = bias[e * DIM + col];
                    else                bofs = bias[col];
                    float v = myStage[r * 20 + c] * invS + bofs;
                    if (MODE == 0) {
                        g_hsh[(size_t)row * SHID + col] = __float2half(gelu_f(v));
                    } else if (MODE == 1) {
                        outp[(size_t)row * DIM + col] = v;
                    } else if (MODE == 2) {
                        unsigned entry = sEnt[lr];
                        int token = entry >> 1, slot = entry & 1;
                        g_hr[((size_t)slot * NTOK + token) * HID + col] = __float2half(gelu_f(v));
                    } else {
                        unsigned entry = sEnt[lr];
                        int token = entry >> 1, slot = entry & 1;
                        g_rout[((size_t)slot * NTOK + token) * DIM + col] = sGate[lr] * v;
                    }
                }
            }
            __syncwarp();
        }
    }
}

// ---------------- final combine: out += routed slot0 + slot1 ----------------
__global__ void combine_kernel(float* __restrict__ out) {
    const size_t n = (size_t)NTOK * DIM;
    size_t i  = (size_t)blockIdx.x * blockDim.x + threadIdx.x;
    size_t st = (size_t)gridDim.x * blockDim.x;
    for (; i < n; i += st)
        out[i] = out[i] + g_rout[i] + g_rout[n + i];
}

// ---------------- launch ----------------
extern "C" void kernel_launch(void* const* d_in, const int* in_sizes, int n_in,
                              void* d_out, int out_size) {
    const float* x   = (const float*)d_in[0];
    const float* gw  = (const float*)d_in[1];
    const float* w1  = (const float*)d_in[2];
    const float* b1  = (const float*)d_in[3];
    const float* w2  = (const float*)d_in[4];
    const float* b2  = (const float*)d_in[5];
    const float* sw1 = (const float*)d_in[6];
    const float* sb1 = (const float*)d_in[7];
    const float* sw2 = (const float*)d_in[8];
    const float* sb2 = (const float*)d_in[9];
    float* out = (float*)d_out;

    zero_cnt_kernel<<<1, 32>>>();
    conv_x  <<<2048, 256>>>(x);
    conv_w1 <<<2048, 256>>>(w1);
    conv_w2 <<<2048, 256>>>(w2);
    conv_sw1<<<1024, 256>>>(sw1);
    conv_sw2<<<1024, 256>>>(sw2);
    gating_kernel<<<NTOK / 8, 256>>>(x, gw);

    // shared expert FFN
    gemm_wmma<0><<<dim3(NTOK / BM, SHID / BN), 256>>>(sb1, out);
    gemm_wmma<1><<<dim3(NTOK / BM, DIM / BN), 256>>>(sb2, out);
    // routed experts (grouped; CTAs beyond per-expert count exit early)
    gemm_wmma<2><<<dim3(NTOK / BM, HID / BN, NEXP), 256>>>(b1, out);
    gemm_wmma<3><<<dim3(NTOK / BM, DIM / BN, NEXP), 256>>>(b2, out);

    combine_kernel<<<2048, 256>>>(out);
}

// round 12
// speedup vs baseline: 1.3896x; 1.3896x over previous
#include <cuda_runtime.h>
#include <cuda_fp16.h>
#include <mma.h>
#include <cstdint>

using namespace nvcuda;

#define NTOK 8192
#define DIM  2048
#define HID  1024
#define NEXP 8
#define SHID 2048

// ---------------- scratch (device globals; no allocations) ----------------
__device__ __align__(16) __half g_xh  [(size_t)NTOK * DIM];        // fp16 copy of x
__device__ __align__(16) __half g_w1h [(size_t)NEXP * DIM * HID];  // scaled x1024
__device__ __align__(16) __half g_w2h [(size_t)NEXP * HID * DIM];
__device__ __align__(16) __half g_sw1h[(size_t)DIM * SHID];
__device__ __align__(16) __half g_sw2h[(size_t)SHID * DIM];
__device__ __align__(16) __half g_hsh [(size_t)NTOK * SHID];       // gelu(x@sw1+sb1) fp16
__device__ __align__(16) __half g_hr  [(size_t)2 * NTOK * HID];    // routed hidden [slot][tok][H]
__device__ __align__(16) float  g_rout[(size_t)2 * NTOK * DIM];    // routed out [slot][tok][D]
__device__ int    g_cnt [NEXP];
__device__ int    g_list[NEXP * NTOK];               // entry = token*2 + slot
__device__ float  g_gate[NEXP * NTOK];

// ---------------- helpers ----------------
__device__ __forceinline__ uint32_t smem_u32(const void* p) {
    return (uint32_t)__cvta_generic_to_shared(p);
}
__device__ __forceinline__ void cpa16(uint32_t dst, const void* src, uint32_t srcsize) {
    asm volatile("cp.async.cg.shared.global [%0], [%1], 16, %2;"
                 :: "r"(dst), "l"(src), "r"(srcsize));
}
#define CP_COMMIT() asm volatile("cp.async.commit_group;")
#define CP_WAIT(n)  asm volatile("cp.async.wait_group %0;" :: "n"(n))

__device__ __forceinline__ float gelu_f(float v) {
    return 0.5f * v * (1.0f + erff(v * 0.70710678118654752f));
}

__global__ void zero_cnt_kernel() {
    if (threadIdx.x < NEXP) g_cnt[threadIdx.x] = 0;
}

// ---------------- fp32 -> fp16 conversion kernels (R1 verbatim) ----------------
#define CONV_KERNEL(NAME, DST, NTOT, SCALE)                                      \
__global__ void NAME(const float* __restrict__ src) {                            \
    size_t i = (size_t)blockIdx.x * blockDim.x + threadIdx.x;                    \
    size_t st = (size_t)gridDim.x * blockDim.x;                                  \
    for (; i < (size_t)(NTOT); i += st) DST[i] = __float2half(src[i] * (SCALE)); \
}

CONV_KERNEL(conv_x,   g_xh,   (size_t)NTOK*DIM,      1.0f)
CONV_KERNEL(conv_w1,  g_w1h,  (size_t)NEXP*DIM*HID,  1024.0f)
CONV_KERNEL(conv_w2,  g_w2h,  (size_t)NEXP*HID*DIM,  1024.0f)
CONV_KERNEL(conv_sw1, g_sw1h, (size_t)DIM*SHID,      1024.0f)
CONV_KERNEL(conv_sw2, g_sw2h, (size_t)SHID*DIM,      1024.0f)

// ---------------- gating (R1 verbatim) ----------------
__global__ void gating_kernel(const float* __restrict__ x,
                              const float* __restrict__ gw) {
    int token = blockIdx.x * 8 + (threadIdx.x >> 5);
    int lane  = threadIdx.x & 31;
    if (token >= NTOK) return;

    const float* xr = x + (size_t)token * DIM;
    float acc[NEXP];
    #pragma unroll
    for (int e = 0; e < NEXP; e++) acc[e] = 0.0f;

    for (int d = lane; d < DIM; d += 32) {
        float xv = xr[d];
        const float* g = gw + (size_t)d * NEXP;
        #pragma unroll
        for (int e = 0; e < NEXP; e++) acc[e] += xv * g[e];
    }
    #pragma unroll
    for (int e = 0; e < NEXP; e++) {
        #pragma unroll
        for (int o = 16; o > 0; o >>= 1)
            acc[e] += __shfl_down_sync(0xFFFFFFFFu, acc[e], o);
    }

    if (lane == 0) {
        float m1 = -1e30f, m2 = -1e30f;
        int i1 = 0, i2 = 0;
        #pragma unroll
        for (int e = 0; e < NEXP; e++) {
            float v = acc[e];
            if (v > m1) { m2 = m1; i2 = i1; m1 = v; i1 = e; }
            else if (v > m2) { m2 = v; i2 = e; }
        }
        float g0 = 1.0f / (1.0f + expf(m2 - m1));
        float g1 = 1.0f - g0;

        int p0 = atomicAdd(&g_cnt[i1], 1);
        g_list[i1 * NTOK + p0] = token * 2 + 0;
        g_gate[i1 * NTOK + p0] = g0;
        int p1 = atomicAdd(&g_cnt[i2], 1);
        g_list[i2 * NTOK + p1] = token * 2 + 1;
        g_gate[i2 * NTOK + p1] = g1;
    }
}

// ---------------- wmma GEMM: R1 math, cp.async double-buffered loads ----------------
// MODE 0: shared layer1:  A=g_xh  [8192,2048], B=g_sw1h [2048,2048] -> gelu -> g_hsh (fp16)
// MODE 1: shared layer2:  A=g_hsh [8192,2048], B=g_sw2h [2048,2048] -> +sb2 -> d_out (fp32)
// MODE 2: routed layer1:  A=gather(g_xh),      B=g_w1h[e][2048,1024] -> gelu -> g_hr
// MODE 3: routed layer2:  A=gather(g_hr),      B=g_w2h[e][1024,2048] -> gate*(acc+b2) -> g_rout
#define BM 128
#define BN 128
#define BK 64
#define SA_LD 72            // halves; 144-byte rows
#define SB_LD 136           // halves; 272-byte rows
#define A_ST (BM * SA_LD * 2)   // 18432 B per stage
#define B_ST (BK * SB_LD * 2)   // 17408 B per stage
#define SMEM_BYTES (2 * A_ST + 2 * B_ST)  // 71680

template<int MODE>
__global__ __launch_bounds__(256)
void gemm_wmma(const float* __restrict__ bias, float* __restrict__ outp) {
    extern __shared__ __align__(16) char dsm[];
    __shared__ const __half* sRow[BM];
    __shared__ unsigned int  sEnt[BM];
    __shared__ float         sGate[BM];

    const int tid    = threadIdx.x;
    const int warpId = tid >> 5;
    const int lane   = tid & 31;

    int e = 0;
    int cnt = NTOK;
    if (MODE >= 2) {
        e = blockIdx.z;
        cnt = g_cnt[e];
        if ((int)blockIdx.x * BM >= cnt) return;
    }
    const int rowBase = blockIdx.x * BM;
    const int colBase = blockIdx.y * BN;

    int K, ldb;
    const __half* Bmat;
    if (MODE == 0) { K = DIM; ldb = SHID; Bmat = g_sw1h; }
    if (MODE == 1) { K = SHID; ldb = DIM; Bmat = g_sw2h; }
    if (MODE == 2) { K = DIM; ldb = HID; Bmat = g_w1h + (size_t)e * DIM * HID; }
    if (MODE == 3) { K = HID; ldb = DIM; Bmat = g_w2h + (size_t)e * HID * DIM; }
    const int KT = K / BK;

    // per-row source pointers + epilogue metadata (R1 verbatim)
    for (int r = tid; r < BM; r += 256) {
        int row = rowBase + r;
        if (MODE == 0)      sRow[r] = g_xh  + (size_t)row * DIM;
        else if (MODE == 1) sRow[r] = g_hsh + (size_t)row * SHID;
        else {
            if (row < cnt) {
                int entry = g_list[e * NTOK + row];
                int token = entry >> 1, slot = entry & 1;
                if (MODE == 2) sRow[r] = g_xh + (size_t)token * DIM;
                else           sRow[r] = g_hr + ((size_t)slot * NTOK + token) * HID;
                sEnt[r] = (unsigned)entry;
                if (MODE == 3) sGate[r] = g_gate[e * NTOK + row];
            } else {
                sRow[r] = nullptr;
            }
        }
    }
    __syncthreads();

    const uint32_t sbase = smem_u32(dsm);
    const uint32_t aOff[2] = { 0u, A_ST };
    const uint32_t bOff[2] = { 2u * A_ST, 2u * A_ST + B_ST };

    // cp.async tile loader: A 128x64 halves (gathered rows), B 64x128 halves
    auto load_tile = [&](int kt, int stg) {
        const uint32_t aD = sbase + aOff[stg];
        const uint32_t bD = sbase + bOff[stg];
        #pragma unroll
        for (int it = 0; it < 4; it++) {
            int idx = tid + it * 256;
            int ar = idx >> 3, c8 = idx & 7;
            const __half* p = sRow[ar];
            // invalid rows: srcsize 0 -> zero-fill (same values R1 wrote)
            cpa16(aD + ar * (SA_LD * 2) + c8 * 16,
                  p ? (p + kt + c8 * 8) : (const __half*)g_xh,
                  p ? 16u : 0u);
        }
        #pragma unroll
        for (int it = 0; it < 4; it++) {
            int idx = tid + it * 256;
            int br = idx >> 4, c8 = idx & 15;
            cpa16(bD + br * (SB_LD * 2) + c8 * 16,
                  Bmat + (size_t)(kt + br) * ldb + colBase + c8 * 8, 16u);
        }
    };

    wmma::fragment<wmma::accumulator, 16, 16, 16, float> acc[2][4];
    #pragma unroll
    for (int mi = 0; mi < 2; mi++)
        #pragma unroll
        for (int ni = 0; ni < 4; ni++)
            wmma::fill_fragment(acc[mi][ni], 0.0f);

    const int wm = warpId >> 1;  // 0..3
    const int wn = warpId & 1;   // 0..1

    load_tile(0, 0);
    CP_COMMIT();

    for (int k = 0; k < KT; k++) {
        const int stg = k & 1;
        if (k + 1 < KT) { load_tile((k + 1) * BK, stg ^ 1); CP_COMMIT(); CP_WAIT(1); }
        else            { CP_WAIT(0); }
        __syncthreads();   // stage stg filled for all threads

        const __half* sA = (const __half*)(dsm + aOff[stg]);
        const __half* sB = (const __half*)(dsm + bOff[stg]);
        #pragma unroll
        for (int ks = 0; ks < 4; ks++) {
            wmma::fragment<wmma::matrix_a, 16, 16, 16, __half, wmma::row_major> fa[2];
            wmma::fragment<wmma::matrix_b, 16, 16, 16, __half, wmma::row_major> fb[4];
            #pragma unroll
            for (int mi = 0; mi < 2; mi++)
                wmma::load_matrix_sync(fa[mi], sA + (wm * 32 + mi * 16) * SA_LD + ks * 16, SA_LD);
            #pragma unroll
            for (int ni = 0; ni < 4; ni++)
                wmma::load_matrix_sync(fb[ni], sB + (ks * 16) * SB_LD + wn * 64 + ni * 16, SB_LD);
            #pragma unroll
            for (int mi = 0; mi < 2; mi++)
                #pragma unroll
                for (int ni = 0; ni < 4; ni++)
                    wmma::mma_sync(acc[mi][ni], fa[mi], fb[ni], acc[mi][ni]);
        }
        __syncthreads();   // all warps done with stage stg before it is refilled
    }

    // epilogue (R1 verbatim): stage through smem, apply bias/gelu/gate, store
    float* stage   = (float*)dsm;
    float* myStage = stage + warpId * 16 * 20;
    const float invS = 1.0f / 1024.0f;  // undo weight scaling

    #pragma unroll
    for (int mi = 0; mi < 2; mi++) {
        #pragma unroll
        for (int ni = 0; ni < 4; ni++) {
            wmma::store_matrix_sync(myStage, acc[mi][ni], 20, wmma::mem_row_major);
            __syncwarp();
            #pragma unroll
            for (int t = lane; t < 256; t += 32) {
                int r = t >> 4, c = t & 15;
                int lr  = wm * 32 + mi * 16 + r;
                int row = rowBase + lr;
                int col = colBase + wn * 64 + ni * 16 + c;
                bool valid = (MODE < 2) || (row < cnt);
                if (valid) {
                    float bofs;
                    if (MODE == 2)      bofs = bias[e * HID + col];
                    else if (MODE == 3) bofs = bias[e * DIM + col];
                    else                bofs = bias[col];
                    float v = myStage[r * 20 + c] * invS + bofs;
                    if (MODE == 0) {
                        g_hsh[(size_t)row * SHID + col] = __float2half(gelu_f(v));
                    } else if (MODE == 1) {
                        outp[(size_t)row * DIM + col] = v;
                    } else if (MODE == 2) {
                        unsigned entry = sEnt[lr];
                        int token = entry >> 1, slot = entry & 1;
                        g_hr[((size_t)slot * NTOK + token) * HID + col] = __float2half(gelu_f(v));
                    } else {
                        unsigned entry = sEnt[lr];
                        int token = entry >> 1, slot = entry & 1;
                        g_rout[((size_t)slot * NTOK + token) * DIM + col] = sGate[lr] * v;
                    }
                }
            }
            __syncwarp();
        }
    }
}

// ---------------- final combine: out += routed slot0 + slot1 (R1 verbatim) ----------------
__global__ void combine_kernel(float* __restrict__ out) {
    const size_t n = (size_t)NTOK * DIM;
    size_t i  = (size_t)blockIdx.x * blockDim.x + threadIdx.x;
    size_t st = (size_t)gridDim.x * blockDim.x;
    for (; i < n; i += st)
        out[i] = out[i] + g_rout[i] + g_rout[n + i];
}

// ---------------- launch ----------------
extern "C" void kernel_launch(void* const* d_in, const int* in_sizes, int n_in,
                              void* d_out, int out_size) {
    const float* x   = (const float*)d_in[0];
    const float* gw  = (const float*)d_in[1];
    const float* w1  = (const float*)d_in[2];
    const float* b1  = (const float*)d_in[3];
    const float* w2  = (const float*)d_in[4];
    const float* b2  = (const float*)d_in[5];
    const float* sw1 = (const float*)d_in[6];
    const float* sb1 = (const float*)d_in[7];
    const float* sw2 = (const float*)d_in[8];
    const float* sb2 = (const float*)d_in[9];
    float* out = (float*)d_out;

    cudaFuncSetAttribute(gemm_wmma<0>, cudaFuncAttributeMaxDynamicSharedMemorySize, SMEM_BYTES);
    cudaFuncSetAttribute(gemm_wmma<1>, cudaFuncAttributeMaxDynamicSharedMemorySize, SMEM_BYTES);
    cudaFuncSetAttribute(gemm_wmma<2>, cudaFuncAttributeMaxDynamicSharedMemorySize, SMEM_BYTES);
    cudaFuncSetAttribute(gemm_wmma<3>, cudaFuncAttributeMaxDynamicSharedMemorySize, SMEM_BYTES);

    zero_cnt_kernel<<<1, 32>>>();
    conv_x  <<<2048, 256>>>(x);
    conv_w1 <<<2048, 256>>>(w1);
    conv_w2 <<<2048, 256>>>(w2);
    conv_sw1<<<1024, 256>>>(sw1);
    conv_sw2<<<1024, 256>>>(sw2);
    gating_kernel<<<NTOK / 8, 256>>>(x, gw);

    // shared expert FFN
    gemm_wmma<0><<<dim3(NTOK / BM, SHID / BN), 256, SMEM_BYTES>>>(sb1, out);
    gemm_wmma<1><<<dim3(NTOK / BM, DIM / BN), 256, SMEM_BYTES>>>(sb2, out);
    // routed experts (grouped; CTAs beyond per-expert count exit early)
    gemm_wmma<2><<<dim3(NTOK / BM, HID / BN, NEXP), 256, SMEM_BYTES>>>(b1, out);
    gemm_wmma<3><<<dim3(NTOK / BM, DIM / BN, NEXP), 256, SMEM_BYTES>>>(b2, out);

    combine_kernel<<<2048, 256>>>(out);
}